// round 2
// baseline (speedup 1.0000x reference)
#include <cuda_runtime.h>
#include <cstdint>

#define M_DIM 8192
#define N_DIM 4096
#define K_DIM 4096

#define MT 256
#define NT 128
#define KT 32
#define STAGES 4
#define KITERS (K_DIM / KT)          // 128
#define THREADS 256

#define A_STAGE_BYTES (MT * KT * 4)  // 32768
#define B_STAGE_BYTES (NT * KT * 4)  // 16384
#define STAGE_BYTES   (A_STAGE_BYTES + B_STAGE_BYTES)   // 49152
#define SMEM_BYTES    (STAGES * STAGE_BYTES)            // 196608

// Scratch: symmetrized + tf32-rounded weight (bit pattern stored as float)
__device__ float g_wsym[(size_t)N_DIM * K_DIM];

// ---------------- helpers ----------------
__device__ __forceinline__ uint32_t smem_u32(const void* p) {
    uint32_t a;
    asm("{ .reg .u64 t; cvta.to.shared.u64 t, %1; cvt.u32.u64 %0, t; }" : "=r"(a) : "l"(p));
    return a;
}
__device__ __forceinline__ uint32_t f2tf32(float f) {
    uint32_t r;
    asm("cvt.rna.tf32.f32 %0, %1;" : "=r"(r) : "f"(f));
    return r;
}
__device__ __forceinline__ void cp_async16(uint32_t dst, const void* src) {
    asm volatile("cp.async.cg.shared.global [%0], [%1], 16;" :: "r"(dst), "l"(src) : "memory");
}
#define CP_COMMIT() asm volatile("cp.async.commit_group;" ::: "memory")
#define CP_WAIT2()  asm volatile("cp.async.wait_group 2;" ::: "memory")

__device__ __forceinline__ uint32_t lds_u32(uint32_t a) {
    uint32_t v;
    asm volatile("ld.shared.b32 %0, [%1];" : "=r"(v) : "r"(a));
    return v;
}

__device__ __forceinline__ void mma_tf32(float* c, const uint32_t* a, const uint32_t* b) {
    asm volatile(
        "mma.sync.aligned.m16n8k8.row.col.f32.tf32.tf32.f32 "
        "{%0,%1,%2,%3}, {%4,%5,%6,%7}, {%8,%9}, {%0,%1,%2,%3};"
        : "+f"(c[0]), "+f"(c[1]), "+f"(c[2]), "+f"(c[3])
        : "r"(a[0]), "r"(a[1]), "r"(a[2]), "r"(a[3]), "r"(b[0]), "r"(b[1]));
}

// swizzled byte offset within a [rows][32 float] tile (128B rows)
__device__ __forceinline__ uint32_t swz(int row, int k) {
    return (uint32_t)row * 128u + (((uint32_t)k * 4u) ^ (((uint32_t)row & 7u) << 4));
}

// ---------------- symmetrize + tf32-round weight ----------------
__global__ void symmetrize_kernel(const float* __restrict__ w) {
    int idx = blockIdx.x * blockDim.x + threadIdx.x;   // 0 .. 16M-1
    int r = idx >> 12;
    int c = idx & (K_DIM - 1);
    float v;
    if (r < 4092 && c < 4092) {
        int br = r / 12, ir = r - br * 12;
        int bc = c / 12, ic = c - bc * 12;
        float a = w[(size_t)r * K_DIM + c];
        float b = w[(size_t)(br * 12 + ic) * K_DIM + (bc * 12 + ir)];
        v = 0.5f * (a + b);
    } else {
        v = w[(size_t)r * K_DIM + c];
    }
    ((uint32_t*)g_wsym)[idx] = f2tf32(v);
}

// ---------------- main GEMM (tf32 mma.sync + cp.async pipeline) ----------------
__global__ void __launch_bounds__(THREADS, 1)
gemm_tf32_kernel(const float* __restrict__ x, const float* __restrict__ bias,
                 float* __restrict__ out) {
    extern __shared__ char smem[];
    const uint32_t sb = smem_u32(smem);

    const int tid = threadIdx.x;
    const int wid = tid >> 5;
    const int lane = tid & 31;
    const int g = lane >> 2;        // groupID 0..7
    const int tig = lane & 3;       // thread-in-group 0..3

    // warp tile: 64x64; warp grid 4 (m) x 2 (n)
    const int wm0 = (wid & 3) * 64;
    const int wn0 = (wid >> 2) * 64;

    // --- CTA raster: bands of 4 M-tiles over all N (keeps W L2-resident) ---
    const int num_n = N_DIM / NT;              // 32
    const int tiles_per_band = 4 * num_n;      // 128
    int t = blockIdx.x;
    int band = t / tiles_per_band;
    int inb = t - band * tiles_per_band;
    const int m0 = (band * 4 + (inb & 3)) * MT;
    const int n0 = (inb >> 2) * NT;

    // --- producer chunk assignments (16B chunks) ---
    // A: 256 rows x 8 chunks = 2048 chunks, 8 per thread
    // B: 128 rows x 8 chunks = 1024 chunks, 4 per thread

    // --- preload bias ---
    float bias_r[8][2];
    #pragma unroll
    for (int nt = 0; nt < 8; nt++) {
        int n = n0 + wn0 + nt * 8 + 2 * tig;
        bias_r[nt][0] = __ldg(bias + n);
        bias_r[nt][1] = __ldg(bias + n + 1);
    }

    float acc[4][8][4];
    #pragma unroll
    for (int mt = 0; mt < 4; mt++)
        #pragma unroll
        for (int nt = 0; nt < 8; nt++)
            #pragma unroll
            for (int i = 0; i < 4; i++) acc[mt][nt][i] = 0.0f;

    // ---- load issue helper (inlined manually) ----
    auto issue_stage = [&](int s, int kt) {
        const uint32_t aBase = sb + (uint32_t)s * STAGE_BYTES;
        const uint32_t bBase = aBase + A_STAGE_BYTES;
        const int k0 = kt * KT;
        #pragma unroll
        for (int i = 0; i < 8; i++) {
            int id = tid + i * THREADS;          // 0..2047
            int row = id >> 3, ch = id & 7;
            const float* src = x + (size_t)(m0 + row) * K_DIM + k0 + ch * 4;
            uint32_t dst = aBase + (uint32_t)row * 128u + (uint32_t)((ch ^ (row & 7)) << 4);
            cp_async16(dst, src);
        }
        #pragma unroll
        for (int i = 0; i < 4; i++) {
            int id = tid + i * THREADS;          // 0..1023
            int row = id >> 3, ch = id & 7;
            const float* src = g_wsym + (size_t)(n0 + row) * K_DIM + k0 + ch * 4;
            uint32_t dst = bBase + (uint32_t)row * 128u + (uint32_t)((ch ^ (row & 7)) << 4);
            cp_async16(dst, src);
        }
        CP_COMMIT();
    };

    // ---- prologue: fill 3 stages ----
    issue_stage(0, 0);
    issue_stage(1, 1);
    issue_stage(2, 2);

    // ---- mainloop ----
    for (int kt = 0; kt < KITERS; kt++) {
        CP_WAIT2();
        __syncthreads();

        if (kt + 3 < KITERS) {
            issue_stage((kt + 3) & 3, kt + 3);
        } else {
            CP_COMMIT();   // keep group count consistent
        }

        const int s = kt & 3;
        const uint32_t aW = sb + (uint32_t)s * STAGE_BYTES + (uint32_t)wm0 * 128u;
        const uint32_t bW = sb + (uint32_t)s * STAGE_BYTES + A_STAGE_BYTES + (uint32_t)wn0 * 128u;

        #pragma unroll
        for (int ks = 0; ks < 4; ks++) {
            const int kb = ks * 8;
            uint32_t af[4][4];
            uint32_t bf[8][2];
            #pragma unroll
            for (int mt = 0; mt < 4; mt++) {
                int r = mt * 16 + g;
                af[mt][0] = lds_u32(aW + swz(r,     kb + tig));
                af[mt][1] = lds_u32(aW + swz(r + 8, kb + tig));
                af[mt][2] = lds_u32(aW + swz(r,     kb + tig + 4));
                af[mt][3] = lds_u32(aW + swz(r + 8, kb + tig + 4));
            }
            #pragma unroll
            for (int nt = 0; nt < 8; nt++) {
                int r = nt * 8 + g;
                bf[nt][0] = lds_u32(bW + swz(r, kb + tig));
                bf[nt][1] = lds_u32(bW + swz(r, kb + tig + 4));
            }
            #pragma unroll
            for (int mt = 0; mt < 4; mt++)
                #pragma unroll
                for (int nt = 0; nt < 8; nt++)
                    mma_tf32(acc[mt][nt], af[mt], bf[nt]);
        }
    }

    // ---- epilogue: bias + store ----
    #pragma unroll
    for (int mt = 0; mt < 4; mt++) {
        int m = m0 + wm0 + mt * 16 + g;
        float* r0 = out + (size_t)m * N_DIM + n0 + wn0;
        float* r1 = r0 + (size_t)8 * N_DIM;
        #pragma unroll
        for (int nt = 0; nt < 8; nt++) {
            float2 v0, v1;
            v0.x = acc[mt][nt][0] + bias_r[nt][0];
            v0.y = acc[mt][nt][1] + bias_r[nt][1];
            v1.x = acc[mt][nt][2] + bias_r[nt][0];
            v1.y = acc[mt][nt][3] + bias_r[nt][1];
            *(float2*)(r0 + nt * 8 + 2 * tig) = v0;
            *(float2*)(r1 + nt * 8 + 2 * tig) = v1;
        }
    }
}

// ---------------- launch ----------------
extern "C" void kernel_launch(void* const* d_in, const int* in_sizes, int n_in,
                              void* d_out, int out_size) {
    const float* x = (const float*)d_in[0];       // [8192, 4096]
    const float* w = (const float*)d_in[1];       // [4096, 4096]
    const float* bias = (const float*)d_in[2];    // [4096]
    float* out = (float*)d_out;                   // [8192, 4096]

    symmetrize_kernel<<<(N_DIM * K_DIM) / 256, 256>>>(w);

    cudaFuncSetAttribute(gemm_tf32_kernel,
                         cudaFuncAttributeMaxDynamicSharedMemorySize, SMEM_BYTES);
    const int grid = (M_DIM / MT) * (N_DIM / NT);  // 1024
    gemm_tf32_kernel<<<grid, THREADS, SMEM_BYTES>>>(x, bias, out);
}